// round 15
// baseline (speedup 1.0000x reference)
#include <cuda_runtime.h>
#include <cuda_fp16.h>
#include <cstdint>

#define HWP 3600
#define NBATCH 2
#define CDIM 256
#define KNN 64
#define M_TOTAL (NBATCH*HWP)   // 7200
#define MPAD 7296              // padded rows (multiple of 128)

// ---------------- scratch (device globals; no allocation allowed) ----------
__device__ __half g_m[MPAD*CDIM];       // relu(mlp(h)) fp16
__device__ float g_tmp[MPAD*CDIM];      // h @ Wa^T fp32
__device__ float g_h[MPAD*CDIM];        // fp32 h (for final readout)
__device__ __half g_Ah[MPAD*CDIM], g_Al[MPAD*CDIM];   // h split (fp16 hi/lo)
__device__ __half g_Mh[MPAD*CDIM], g_Ml[MPAD*CDIM];   // msg split
__device__ __half g_Wmh[CDIM*CDIM];                   // mlp_w hi
__device__ __half g_Wah[CDIM*CDIM];                   // rnn_w[:, :C] hi
__device__ __half g_Wbh[CDIM*CDIM];                   // rnn_w[:, C:] hi
__device__ int   g_idx[M_TOTAL*KNN];

// fp16 hi/lo split: v ~= h + l with combined 22-bit mantissa
__device__ __forceinline__ void hsplit(float v, __half& h, __half& l){
    h = __float2half_rn(v);
    l = __float2half_rn(v - __half2float(h));
}

__device__ __forceinline__ uint32_t smem_u32(const void* p) {
    uint32_t a;
    asm("{ .reg .u64 t; cvta.to.shared.u64 t, %1; cvt.u32.u64 %0, t; }" : "=r"(a) : "l"(p));
    return a;
}

// ---------------- mma.sync helpers (suffix-neutral PTX, tensor pipe) -------
__device__ __forceinline__ void ldmat4(uint32_t r[4], uint32_t addr){
    asm volatile("ldmatrix.sync.aligned.m8n8.x4.shared.b16 {%0,%1,%2,%3}, [%4];"
        : "=r"(r[0]), "=r"(r[1]), "=r"(r[2]), "=r"(r[3]) : "r"(addr));
}
__device__ __forceinline__ void mma16816(float c[4], const uint32_t a[4],
                                         uint32_t b0, uint32_t b1){
    asm volatile("mma.sync.aligned.m16n8k16.row.col.f32.f16.f16.f32 "
        "{%0,%1,%2,%3}, {%4,%5,%6,%7}, {%8,%9}, {%0,%1,%2,%3};"
        : "+f"(c[0]), "+f"(c[1]), "+f"(c[2]), "+f"(c[3])
        : "r"(a[0]), "r"(a[1]), "r"(a[2]), "r"(a[3]), "r"(b0), "r"(b1));
}

// smem tile layout: padded stride 72 fp16 (144B = 9 x 16B -> conflict-free)
#define ASTRIDE 72
#define OFF_AH  0
#define OFF_AL  18432
#define OFF_BH  36864
#define GEMM_SMEM 46080

// ---- 128x64x256 tile: fp16 split via mma.sync, fp32 accumulate ------------
// USE_AL (compile-time): include the Al*Bh correction term (2-term split).
template <bool USE_AL>
__device__ void tile_mma(const __half* __restrict__ Ah,
                         const __half* __restrict__ Al,
                         const __half* __restrict__ Bh,
                         int m0, float acc[2][4][4])
{
    extern __shared__ char smem[];
    const uint32_t sb = smem_u32(smem);
    const int tid = threadIdx.x;
    const int lane = tid & 31;
    const int wid = tid >> 5;
    const int wm = wid & 3;        // m32 section
    const int wn = wid >> 2;       // n32 section

    #pragma unroll
    for (int mt = 0; mt < 2; ++mt)
        #pragma unroll
        for (int nt = 0; nt < 4; ++nt)
            #pragma unroll
            for (int q = 0; q < 4; ++q) acc[mt][nt][q] = 0.f;

    const uint32_t aoff = (uint32_t)(((lane & 15)*ASTRIDE + (lane >> 4)*8) * 2);
    const uint32_t boff = (uint32_t)((((lane & 7) + ((lane >> 4) << 3))*ASTRIDE
                                      + ((lane >> 3) & 1)*8) * 2);

    constexpr int NV = USE_AL ? 10 : 6;   // copy items: A(4) [+Al(4)] +B(2)

    #pragma unroll 1
    for (int kc = 0; kc < 4; ++kc) {
        #pragma unroll
        for (int i = 0; i < NV; ++i) {
            int v = tid + i*256;
            const uint4* src;
            uint32_t dst;
            if (v < 1024) {
                int row = v >> 3, c8 = v & 7;
                src = (const uint4*)(Ah + (m0 + row)*CDIM + kc*64 + c8*8);
                dst = OFF_AH + (uint32_t)(row*ASTRIDE + c8*8)*2;
            } else if (USE_AL && v < 2048) {
                int u = v - 1024, row = u >> 3, c8 = u & 7;
                src = (const uint4*)(Al + (m0 + row)*CDIM + kc*64 + c8*8);
                dst = OFF_AL + (uint32_t)(row*ASTRIDE + c8*8)*2;
            } else {
                int u = v - (USE_AL ? 2048 : 1024);
                int row = u >> 3, c8 = u & 7;
                src = (const uint4*)(Bh + row*CDIM + kc*64 + c8*8);
                dst = OFF_BH + (uint32_t)(row*ASTRIDE + c8*8)*2;
            }
            *(uint4*)(smem + dst) = *src;
        }
        __syncthreads();

        #pragma unroll
        for (int ks = 0; ks < 4; ++ks) {
            const uint32_t abase = (uint32_t)((wm*32*ASTRIDE + ks*16) * 2);
            const uint32_t bbase = (uint32_t)((wn*32*ASTRIDE + ks*16) * 2);
            const uint32_t mstep = (uint32_t)(16*ASTRIDE*2);

            uint32_t ah0[4], ah1[4];
            ldmat4(ah0, sb + OFF_AH + abase + aoff);
            ldmat4(ah1, sb + OFF_AH + abase + mstep + aoff);

            uint32_t bhA[4], bhB[4];
            ldmat4(bhA, sb + OFF_BH + bbase + boff);
            ldmat4(bhB, sb + OFF_BH + bbase + mstep + boff);

            mma16816(acc[0][0], ah0, bhA[0], bhA[1]);
            mma16816(acc[0][1], ah0, bhA[2], bhA[3]);
            mma16816(acc[0][2], ah0, bhB[0], bhB[1]);
            mma16816(acc[0][3], ah0, bhB[2], bhB[3]);
            mma16816(acc[1][0], ah1, bhA[0], bhA[1]);
            mma16816(acc[1][1], ah1, bhA[2], bhA[3]);
            mma16816(acc[1][2], ah1, bhB[0], bhB[1]);
            mma16816(acc[1][3], ah1, bhB[2], bhB[3]);

            if constexpr (USE_AL) {
                uint32_t al0[4], al1[4];
                ldmat4(al0, sb + OFF_AL + abase + aoff);
                ldmat4(al1, sb + OFF_AL + abase + mstep + aoff);
                mma16816(acc[0][0], al0, bhA[0], bhA[1]);
                mma16816(acc[0][1], al0, bhA[2], bhA[3]);
                mma16816(acc[0][2], al0, bhB[0], bhB[1]);
                mma16816(acc[0][3], al0, bhB[2], bhB[3]);
                mma16816(acc[1][0], al1, bhA[0], bhA[1]);
                mma16816(acc[1][1], al1, bhA[2], bhA[3]);
                mma16816(acc[1][2], al1, bhB[0], bhB[1]);
                mma16816(acc[1][3], al1, bhB[2], bhB[3]);
            }
        }
        __syncthreads();
    }
}

// GEMM1m: m = relu(h Wmlp^T + b)  (fp16 out, 1-term split)
__global__ void __launch_bounds__(256) gemm1m_kernel(const float* __restrict__ mlp_b)
{
    int m0 = blockIdx.x * 128;
    int d0 = blockIdx.y * 64;

    float acc[2][4][4];
    tile_mma<false>(g_Ah, g_Al, g_Wmh + d0*CDIM, m0, acc);

    int lane = threadIdx.x & 31, wid = threadIdx.x >> 5;
    int wm = wid & 3, wn = wid >> 2;
    int g = lane >> 2, t = lane & 3;

    #pragma unroll
    for (int mt = 0; mt < 2; ++mt) {
        #pragma unroll
        for (int nt = 0; nt < 4; ++nt) {
            int n = d0 + wn*32 + nt*8 + t*2;
            float bx = mlp_b[n], byv = mlp_b[n+1];
            #pragma unroll
            for (int half = 0; half < 2; ++half) {
                int m = m0 + wm*32 + mt*16 + g + half*8;
                if (m >= M_TOTAL) continue;
                float vx = fmaxf(acc[mt][nt][half*2+0] + bx, 0.f);
                float vy = fmaxf(acc[mt][nt][half*2+1] + byv, 0.f);
                *(__half2*)(g_m + m*CDIM + n) =
                    __halves2half2(__float2half_rn(vx), __float2half_rn(vy));
            }
        }
    }
}

// GEMM1t: tmp = h Wa^T  (fp32 out, 2-term split)
__global__ void __launch_bounds__(256) gemm1t_kernel(float* __restrict__ tmp_out)
{
    int m0 = blockIdx.x * 128;
    int d0 = blockIdx.y * 64;

    float acc[2][4][4];
    tile_mma<true>(g_Ah, g_Al, g_Wah + d0*CDIM, m0, acc);

    int lane = threadIdx.x & 31, wid = threadIdx.x >> 5;
    int wm = wid & 3, wn = wid >> 2;
    int g = lane >> 2, t = lane & 3;

    #pragma unroll
    for (int mt = 0; mt < 2; ++mt) {
        #pragma unroll
        for (int nt = 0; nt < 4; ++nt) {
            int n = d0 + wn*32 + nt*8 + t*2;
            #pragma unroll
            for (int half = 0; half < 2; ++half) {
                int m = m0 + wm*32 + mt*16 + g + half*8;
                if (m >= M_TOTAL) continue;
                *(float2*)(tmp_out + m*CDIM + n) =
                    make_float2(acc[mt][nt][half*2+0], acc[mt][nt][half*2+1]);
            }
        }
    }
}

// GEMM3: h' = relu(tmp + msg Wb^T + b_rnn); writes fp32 h and fp16 split
__global__ void __launch_bounds__(256) gemm3_kernel(const float* __restrict__ rnn_b,
                                                    const float* __restrict__ tmp,
                                                    float* __restrict__ h_out)
{
    int m0 = blockIdx.x * 128;
    int d0 = blockIdx.y * 64;

    float acc[2][4][4];
    tile_mma<true>(g_Mh, g_Ml, g_Wbh + d0*CDIM, m0, acc);

    int lane = threadIdx.x & 31, wid = threadIdx.x >> 5;
    int wm = wid & 3, wn = wid >> 2;
    int g = lane >> 2, t = lane & 3;

    #pragma unroll
    for (int mt = 0; mt < 2; ++mt) {
        #pragma unroll
        for (int nt = 0; nt < 4; ++nt) {
            int n = d0 + wn*32 + nt*8 + t*2;
            float bx = rnn_b[n], byv = rnn_b[n+1];
            #pragma unroll
            for (int half = 0; half < 2; ++half) {
                int m = m0 + wm*32 + mt*16 + g + half*8;
                if (m >= M_TOTAL) continue;
                float2 tv = *(const float2*)(tmp + m*CDIM + n);
                float vx = fmaxf(acc[mt][nt][half*2+0] + tv.x + bx, 0.f);
                float vy = fmaxf(acc[mt][nt][half*2+1] + tv.y + byv, 0.f);
                *(float2*)(h_out + m*CDIM + n) = make_float2(vx, vy);
                __half hx, lx, hy, ly;
                hsplit(vx, hx, lx); hsplit(vy, hy, ly);
                *(__half2*)(g_Ah + m*CDIM + n) = __halves2half2(hx, hy);
                *(__half2*)(g_Al + m*CDIM + n) = __halves2half2(lx, ly);
            }
        }
    }
}

// -------- weight conversion + pad-row zeroing (once per call) --------------
__global__ void __launch_bounds__(256) wconv_kernel(const float* __restrict__ mlp_w,
                                                    const float* __restrict__ rnn_w)
{
    int e = blockIdx.x * 256 + threadIdx.x;   // < 256*768
    if (e < CDIM*CDIM) {
        g_Wmh[e] = __float2half_rn(mlp_w[e]);
    } else {
        int u = e - CDIM*CDIM;                 // < 256*512
        int r = u >> 9, c = u & 511;
        __half h = __float2half_rn(rnn_w[u]);
        if (c < CDIM) g_Wah[r*CDIM + c] = h;
        else          g_Wbh[r*CDIM + c - CDIM] = h;
    }
    if (e < (MPAD - M_TOTAL)*CDIM) {           // zero pad rows (96*256)
        int o = M_TOTAL*CDIM + e;
        g_Ah[o] = __float2half(0.f); g_Al[o] = __float2half(0.f);
        g_Mh[o] = __float2half(0.f); g_Ml[o] = __float2half(0.f);
    }
}

// -- cnn (n,c,s) -> Ah/Al (n,s,c) fp16 split + out[:, :256] copy (fused) ----
__global__ void __launch_bounds__(256) tin_kernel(const float* __restrict__ cnn,
                                                  float* __restrict__ out)
{
    __shared__ float tile[32][65];                   // [s_l][c_l], pad 65
    int s0 = blockIdx.x * 32;
    int c0 = blockIdx.y * 64;
    int bn = blockIdx.z;
    const float* src = cnn + ((size_t)bn*CDIM + c0)*HWP + s0;
    float* dst = out + ((size_t)bn*(2*CDIM) + c0)*HWP + s0;

    #pragma unroll
    for (int i = 0; i < 8; ++i) {
        int flat = threadIdx.x + i*256;              // 0..2047
        int s_l = flat & 31, c_l = flat >> 5;
        float v = 0.f;
        if (s0 + s_l < HWP) {
            v = src[(size_t)c_l*HWP + s_l];
            dst[(size_t)c_l*HWP + s_l] = v;          // out[:, :256] = cnn
        }
        tile[s_l][c_l] = v;
    }
    __syncthreads();

    #pragma unroll
    for (int i = 0; i < 4; ++i) {
        int flat = threadIdx.x + i*256;              // 0..1023 (half2 units)
        int cp = flat & 31;                          // c = cp*2
        int s_l = flat >> 5;
        int s = s0 + s_l;
        if (s >= HWP) continue;
        float v0 = tile[s_l][cp*2], v1 = tile[s_l][cp*2+1];
        __half h0, l0, h1, l1;
        hsplit(v0, h0, l0); hsplit(v1, h1, l1);
        int o = (bn*HWP + s)*CDIM + c0 + cp*2;
        *(__half2*)(g_Ah + o) = __halves2half2(h0, h1);
        *(__half2*)(g_Al + o) = __halves2half2(l0, l1);
    }
}

// ------- h (n,s,c) -> out[:, 256:512] (n,c,s), smem tile transpose ---------
__global__ void __launch_bounds__(256) tout_kernel(const float* __restrict__ h,
                                                   float* __restrict__ out)
{
    __shared__ float tile[64][33];                   // [c_l][s_l], pad 33
    int s0 = blockIdx.x * 32;
    int c0 = blockIdx.y * 64;
    int bn = blockIdx.z;

    #pragma unroll
    for (int i = 0; i < 8; ++i) {
        int flat = threadIdx.x + i*256;
        int c_l = flat & 63, s_l = flat >> 6;        // s_l 0..31
        int s = s0 + s_l;
        float v = 0.f;
        if (s < HWP) v = h[((size_t)bn*HWP + s)*CDIM + c0 + c_l];
        tile[c_l][s_l] = v;
    }
    __syncthreads();

    #pragma unroll
    for (int i = 0; i < 8; ++i) {
        int flat = threadIdx.x + i*256;
        int s_l = flat & 31, c_l = flat >> 5;        // c_l 0..63
        int s = s0 + s_l;
        if (s < HWP)
            out[((size_t)bn*(2*CDIM) + CDIM + c0 + c_l)*HWP + s] = tile[c_l][s_l];
    }
}

// ---------------- KNN v6: candidate-major, 4 rows/block ---------------------
#define KNN_BR 4
#define CAP 192
// dynamic smem layout (bytes)
#define KPX    0                        // float[3600]  14400
#define KPY    14400
#define KPZ    28800                    // end 43200
#define KHIST  43200                    // int[4][256]   4096
#define KCV    47296                    // u32[4][CAP]   3072
#define KCI    50368                    // int[4][CAP]   3072
#define KTIE   53440                    // int[4][32]     512
#define KOCNT  53952                    // int[4]
#define KCCNT  53968                    // int[4]
#define KECRIT 53984                    // int[4]
#define KFLAG  54000                    // int[4]
#define KWS    54016                    // int[2][8]
#define KSC    54080                    // int[4]
#define KNN_SMEM 54144

__global__ void __launch_bounds__(256) knn_kernel(const float* __restrict__ pts,
                                                  int* __restrict__ idx_out)
{
    extern __shared__ char sm[];
    float* px = (float*)(sm + KPX);
    float* py = (float*)(sm + KPY);
    float* pz = (float*)(sm + KPZ);
    int* hist = (int*)(sm + KHIST);
    unsigned* cv = (unsigned*)(sm + KCV);
    int* ci = (int*)(sm + KCI);
    int* tiebuf = (int*)(sm + KTIE);
    int* ocnt  = (int*)(sm + KOCNT);
    int* ccnt  = (int*)(sm + KCCNT);
    int* ecrit = (int*)(sm + KECRIT);
    int* flag  = (int*)(sm + KFLAG);
    int* ws    = (int*)(sm + KWS);
    int* sc    = (int*)(sm + KSC);

    int gb = blockIdx.x;
    int n  = gb / (HWP/KNN_BR);
    int g  = gb % (HWP/KNN_BR);
    int tid = threadIdx.x;
    int lane = tid & 31, wid = tid >> 5;
    const unsigned ltm = (1u << lane) - 1u;

    const float* p = pts + n*3*HWP;
    for (int i = tid; i < HWP; i += 256) {
        px[i] = p[i];
        py[i] = p[i + HWP];
        pz[i] = p[i + 2*HWP];
    }
    #pragma unroll
    for (int i = 0; i < KNN_BR; ++i) hist[i*256 + tid] = 0;
    if (tid < KNN_BR) { ocnt[tid] = 0; ccnt[tid] = 0; flag[tid] = 0; }
    __syncthreads();                                   // B0

    float qx[KNN_BR], qy[KNN_BR], qz[KNN_BR], qs[KNN_BR];
    #pragma unroll
    for (int r = 0; r < KNN_BR; ++r) {
        int row = g*KNN_BR + r;
        qx[r] = px[row]; qy[r] = py[row]; qz[r] = pz[row];
        qs[r] = fmaf(qz[r], qz[r], fmaf(qy[r], qy[r], qx[r]*qx[r]));
    }

    // ---- pass 1: candidate-major, build histograms -------------------------
    #pragma unroll 1
    for (int t = 0; t < 15; ++t) {
        int j = t*256 + tid;
        bool v = j < HWP;
        float x = 0.f, y = 0.f, z = 0.f, sj = 0.f;
        if (v) { x = px[j]; y = py[j]; z = pz[j]; sj = fmaf(z, z, fmaf(y, y, x*x)); }
        #pragma unroll
        for (int r = 0; r < KNN_BR; ++r) {
            unsigned bits = 0x7f800000u;
            if (v) {
                float dot = fmaf(qz[r], z, fmaf(qy[r], y, qx[r]*x));
                bits = __float_as_uint(fmaxf(qs[r] + sj - 2.0f*dot, 0.0f));
            }
            unsigned e = bits >> 23;
            unsigned mask = __match_any_sync(0xffffffffu, e);
            if (lane == (unsigned)(__ffs(mask) - 1)) atomicAdd(&hist[r*256 + e], __popc(mask));
        }
    }
    __syncthreads();                                   // B1

    // ---- scan: warp w scans hist[w] ----------------------------------------
    if (wid < KNN_BR) {
        int* h4 = hist + wid*256;
        int basebin = lane*8, loc[8], ssum = 0;
        #pragma unroll
        for (int j2 = 0; j2 < 8; ++j2) { loc[j2] = h4[basebin + j2]; ssum += loc[j2]; }
        int pre = ssum;
        #pragma unroll
        for (int o = 1; o < 32; o <<= 1) {
            int v2 = __shfl_up_sync(0xffffffffu, pre, o);
            if (lane >= (unsigned)o) pre += v2;
        }
        int excl = pre - ssum;
        int ec = 0;
        if (excl < KNN && excl + ssum >= KNN) {        // unique crossing lane
            int cum = excl;
            #pragma unroll
            for (int j2 = 0; j2 < 8; ++j2) {
                if (cum + loc[j2] >= KNN) { ec = basebin + j2; break; }
                cum += loc[j2];
            }
        }
        ec = __reduce_max_sync(0xffffffffu, ec);
        if (lane == 0) ecrit[wid] = ec;
    }
    __syncthreads();                                   // B2

    int Ereg[KNN_BR];
    #pragma unroll
    for (int r = 0; r < KNN_BR; ++r) Ereg[r] = ecrit[r];

    // ---- pass 2: recompute, ballot-aggregated compaction -------------------
    #pragma unroll 1
    for (int t = 0; t < 15; ++t) {
        int j = t*256 + tid;
        bool v = j < HWP;
        float x = 0.f, y = 0.f, z = 0.f, sj = 0.f;
        if (v) { x = px[j]; y = py[j]; z = pz[j]; sj = fmaf(z, z, fmaf(y, y, x*x)); }
        #pragma unroll
        for (int r = 0; r < KNN_BR; ++r) {
            unsigned bits = 0x7f800000u;
            if (v) {
                float dot = fmaf(qz[r], z, fmaf(qy[r], y, qx[r]*x));
                bits = __float_as_uint(fmaxf(qs[r] + sj - 2.0f*dot, 0.0f));
            }
            int e = (int)(bits >> 23);
            bool win = v && e < Ereg[r];
            unsigned mw = __ballot_sync(0xffffffffu, win);
            if (mw) {
                int src = __ffs(mw) - 1;
                int base = 0;
                if (lane == (unsigned)src) base = atomicAdd(&ocnt[r], __popc(mw));
                base = __shfl_sync(0xffffffffu, base, src);
                if (win) idx_out[(n*HWP + g*KNN_BR + r)*KNN + base + __popc(mw & ltm)] = j;
            }
            bool cand = v && e == Ereg[r];
            unsigned mc = __ballot_sync(0xffffffffu, cand);
            if (mc) {
                int src = __ffs(mc) - 1;
                int base = 0;
                if (lane == (unsigned)src) base = atomicAdd(&ccnt[r], __popc(mc));
                base = __shfl_sync(0xffffffffu, base, src);
                if (cand) {
                    int pos = base + __popc(mc & ltm);
                    if (pos < CAP) { cv[r*CAP + pos] = bits; ci[r*CAP + pos] = j; }
                }
            }
        }
    }
    __syncthreads();                                   // B3

    // ---- phase B: one row per warp (warps 0..3) ------------------------------
    if (wid < KNN_BR) {
        int r = wid;
        int row = g*KNN_BR + r;
        int* outp = idx_out + (n*HWP + row)*KNN;
        unsigned* wcv = cv + r*CAP;
        int* wci = ci + r*CAP;
        int* wtie = tiebuf + r*32;

        int oc0 = ocnt[r], cc = ccnt[r];
        int Kp = KNN - oc0;

        if (cc > CAP) {
            if (lane == 0) flag[r] = 1;
        } else if (cc == Kp) {
            for (int i = lane; i < cc; i += 32) outp[oc0 + i] = wci[i];
        } else {
            unsigned T = ((unsigned)Ereg[r]) << 23;
            for (int bit = 22; bit >= 0; --bit) {
                unsigned cnd = T | (1u << bit);
                int cnt = 0;
                for (int i = lane; i < cc; i += 32) cnt += (wcv[i] < cnd) ? 1 : 0;
                cnt = __reduce_add_sync(0xffffffffu, cnt);
                if (cnt < Kp) T = cnd;
            }
            int oc = oc0, tc = 0;
            for (int ib = 0; ib < cc; ib += 32) {
                int i = ib + lane;
                bool v = i < cc;
                unsigned bv = v ? wcv[i] : 0xffffffffu;
                unsigned mw = __ballot_sync(0xffffffffu, v && bv < T);
                if (v && bv < T) outp[oc + __popc(mw & ltm)] = wci[i];
                oc += __popc(mw);
                unsigned mt = __ballot_sync(0xffffffffu, v && bv == T);
                if (v && bv == T) {
                    int tp = tc + __popc(mt & ltm);
                    if (tp < 32) wtie[tp] = wci[i];
                }
                tc += __popc(mt);
            }
            __syncwarp();
            if (lane == 0) {
                int slots = KNN - oc;
                int en = tc < 32 ? tc : 32;
                for (int q2 = 0; q2 < slots; ++q2) {   // lowest-index tie fill
                    int best = 0x7fffffff, bi = 0;
                    for (int e2 = 0; e2 < en; ++e2)
                        if (wtie[e2] < best) { best = wtie[e2]; bi = e2; }
                    wtie[bi] = 0x7fffffff;
                    outp[oc + q2] = best;
                }
            }
        }
    }
    __syncthreads();

    // ---- fallback: block-wide 31-bit search (rare) --------------------------
    for (int r = 0; r < KNN_BR; ++r) {
        if (!flag[r]) continue;
        int row = g*KNN_BR + r;
        float fqx = qx[r], fqy = qy[r], fqz = qz[r], fqs = qs[r];

        unsigned d[15];
        #pragma unroll
        for (int t = 0; t < 15; ++t) {
            int j = t*256 + tid;
            if (j < HWP) {
                float x = px[j], y = py[j], z = pz[j];
                float sj  = fmaf(z, z, fmaf(y, y, x*x));
                float dot = fmaf(fqz, z, fmaf(fqy, y, fqx*x));
                d[t] = __float_as_uint(fmaxf(fqs + sj - 2.0f*dot, 0.0f));
            } else {
                d[t] = 0xffffffffu;
            }
        }
        if (tid == 0) { sc[0] = 0; sc[1] = 0; }
        __syncthreads();

        unsigned T = 0;
        for (int bit = 30; bit >= 0; --bit) {
            unsigned cnd = T | (1u << bit);
            int cc2 = 0;
            #pragma unroll
            for (int t = 0; t < 15; ++t) cc2 += (d[t] < cnd) ? 1 : 0;
            cc2 = __reduce_add_sync(0xffffffffu, cc2);
            int par = bit & 1;
            if (lane == 0) ws[par*8 + wid] = cc2;
            __syncthreads();
            int tot = 0;
            #pragma unroll
            for (int w = 0; w < 8; ++w) tot += ws[par*8 + w];
            if (tot < KNN) T = cnd;
        }
        __syncthreads();

        int* outp = idx_out + (n*HWP + row)*KNN;
        int* wtie = tiebuf + r*32;
        #pragma unroll
        for (int t = 0; t < 15; ++t) {
            int j = t*256 + tid;
            unsigned dv = d[t];
            if (dv < T) { int pos = atomicAdd(&sc[0], 1); outp[pos] = j; }
            else if (dv == T && j < HWP) { int pos = atomicAdd(&sc[1], 1); if (pos < 32) wtie[pos] = j; }
        }
        __syncthreads();
        if (tid == 0) {
            int slots = KNN - sc[0];
            int en = sc[1] < 32 ? sc[1] : 32;
            for (int q2 = 0; q2 < slots; ++q2) {
                int best = 0x7fffffff, bi = 0;
                for (int e2 = 0; e2 < en; ++e2)
                    if (wtie[e2] < best) { best = wtie[e2]; bi = e2; }
                wtie[bi] = 0x7fffffff;
                outp[sc[0] + q2] = best;
            }
        }
        __syncthreads();
    }
}

// ------- gather-mean v3: 16 pts/block, 32 thr/pt, 16B loads ----------------
__global__ void __launch_bounds__(512) gather_mean_kernel(const int* __restrict__ idx)
{
    __shared__ int sidx[16*KNN];
    int tid = threadIdx.x;
    int s0 = blockIdx.x * 16;
    sidx[tid]       = idx[s0*KNN + tid];
    sidx[tid + 512] = idx[s0*KNN + tid + 512];
    __syncthreads();

    int lp = tid >> 5;          // 0..15 local point
    int lane = tid & 31;        // 16B chunk (8 halves) within row
    int s = s0 + lp;
    int base = (s / HWP) * HWP;
    const uint4* m4 = reinterpret_cast<const uint4*>(g_m);   // 32 uint4 per row
    const int* ip = sidx + lp*KNN;

    float acc[8];
    #pragma unroll
    for (int i = 0; i < 8; ++i) acc[i] = 0.f;

    #pragma unroll
    for (int k = 0; k < KNN; k += 4) {
        int j0 = ip[k], j1 = ip[k+1], j2 = ip[k+2], j3 = ip[k+3];
        uint4 u0 = m4[(size_t)(base + j0)*32 + lane];
        uint4 u1 = m4[(size_t)(base + j1)*32 + lane];
        uint4 u2 = m4[(size_t)(base + j2)*32 + lane];
        uint4 u3 = m4[(size_t)(base + j3)*32 + lane];
        #pragma unroll
        for (int q = 0; q < 4; ++q) {
            uint4 u = (q == 0) ? u0 : (q == 1) ? u1 : (q == 2) ? u2 : u3;
            float2 f0 = __half22float2(*(__half2*)&u.x);
            float2 f1 = __half22float2(*(__half2*)&u.y);
            float2 f2 = __half22float2(*(__half2*)&u.z);
            float2 f3 = __half22float2(*(__half2*)&u.w);
            acc[0] += f0.x; acc[1] += f0.y; acc[2] += f1.x; acc[3] += f1.y;
            acc[4] += f2.x; acc[5] += f2.y; acc[6] += f3.x; acc[7] += f3.y;
        }
    }
    const float inv = 1.0f / 64.0f;
    __half hh[8], ll[8];
    #pragma unroll
    for (int i = 0; i < 8; ++i) hsplit(acc[i]*inv, hh[i], ll[i]);

    int o = s*CDIM + lane*8;
    __half2 mh0 = __halves2half2(hh[0], hh[1]), mh1 = __halves2half2(hh[2], hh[3]);
    __half2 mh2 = __halves2half2(hh[4], hh[5]), mh3 = __halves2half2(hh[6], hh[7]);
    __half2 ml0 = __halves2half2(ll[0], ll[1]), ml1 = __halves2half2(ll[2], ll[3]);
    __half2 ml2 = __halves2half2(ll[4], ll[5]), ml3 = __halves2half2(ll[6], ll[7]);
    uint4 sh, sl;
    sh.x = *(uint32_t*)&mh0; sh.y = *(uint32_t*)&mh1;
    sh.z = *(uint32_t*)&mh2; sh.w = *(uint32_t*)&mh3;
    sl.x = *(uint32_t*)&ml0; sl.y = *(uint32_t*)&ml1;
    sl.z = *(uint32_t*)&ml2; sl.w = *(uint32_t*)&ml3;
    *(uint4*)(g_Mh + o) = sh;
    *(uint4*)(g_Ml + o) = sl;
}

// ---------------- launcher --------------------------------------------------
extern "C" void kernel_launch(void* const* d_in, const int* in_sizes, int n_in,
                              void* d_out, int out_size)
{
    const float* cnn   = (const float*)d_in[0];
    const float* pts   = (const float*)d_in[1];
    const float* mlp_w = (const float*)d_in[2];
    const float* mlp_b = (const float*)d_in[3];
    const float* rnn_w = (const float*)d_in[4];
    const float* rnn_b = (const float*)d_in[5];
    float* out = (float*)d_out;

    float *tmp, *h;
    int* idx;
    cudaGetSymbolAddress((void**)&tmp, g_tmp);
    cudaGetSymbolAddress((void**)&h,   g_h);
    cudaGetSymbolAddress((void**)&idx, g_idx);

    cudaFuncSetAttribute(gemm1m_kernel, cudaFuncAttributeMaxDynamicSharedMemorySize, GEMM_SMEM);
    cudaFuncSetAttribute(gemm1t_kernel, cudaFuncAttributeMaxDynamicSharedMemorySize, GEMM_SMEM);
    cudaFuncSetAttribute(gemm3_kernel,  cudaFuncAttributeMaxDynamicSharedMemorySize, GEMM_SMEM);
    cudaFuncSetAttribute(knn_kernel,    cudaFuncAttributeMaxDynamicSharedMemorySize, KNN_SMEM);

    wconv_kernel<<<768, 256>>>(mlp_w, rnn_w);
    tin_kernel<<<dim3(113, 4, 2), 256>>>(cnn, out);
    knn_kernel<<<NBATCH*(HWP/KNN_BR), 256, KNN_SMEM>>>(pts, idx);

    for (int it = 0; it < 3; ++it) {
        gemm1m_kernel<<<dim3(MPAD/128, 4), 256, GEMM_SMEM>>>(mlp_b);
        gemm1t_kernel<<<dim3(MPAD/128, 4), 256, GEMM_SMEM>>>(tmp);
        gather_mean_kernel<<<M_TOTAL/16, 512>>>(idx);
        gemm3_kernel<<<dim3(MPAD/128, 4), 256, GEMM_SMEM>>>(rnn_b, tmp, h);
    }
    tout_kernel<<<dim3(113, 4, 2), 256>>>(h, out);
}

// round 16
// speedup vs baseline: 1.0569x; 1.0569x over previous
#include <cuda_runtime.h>
#include <cuda_fp16.h>
#include <cstdint>

#define HWP 3600
#define NBATCH 2
#define CDIM 256
#define KNN 64
#define M_TOTAL (NBATCH*HWP)   // 7200
#define MPAD 7296              // padded rows (multiple of 128)

// ---------------- scratch (device globals; no allocation allowed) ----------
__device__ __half g_m[MPAD*CDIM];       // relu(mlp(h)) fp16
__device__ float g_tmp[MPAD*CDIM];      // h @ Wa^T fp32
__device__ float g_h[MPAD*CDIM];        // fp32 h (for final readout)
__device__ __half g_Ah[MPAD*CDIM], g_Al[MPAD*CDIM];   // h split (fp16 hi/lo)
__device__ __half g_Mh[MPAD*CDIM], g_Ml[MPAD*CDIM];   // msg split
__device__ __half g_Wmh[CDIM*CDIM];                   // mlp_w hi
__device__ __half g_Wah[CDIM*CDIM];                   // rnn_w[:, :C] hi
__device__ __half g_Wbh[CDIM*CDIM];                   // rnn_w[:, C:] hi
__device__ int   g_idx[M_TOTAL*KNN];

// fp16 hi/lo split: v ~= h + l with combined 22-bit mantissa
__device__ __forceinline__ void hsplit(float v, __half& h, __half& l){
    h = __float2half_rn(v);
    l = __float2half_rn(v - __half2float(h));
}

__device__ __forceinline__ uint32_t smem_u32(const void* p) {
    uint32_t a;
    asm("{ .reg .u64 t; cvta.to.shared.u64 t, %1; cvt.u32.u64 %0, t; }" : "=r"(a) : "l"(p));
    return a;
}

// ---------------- mma.sync helpers (suffix-neutral PTX, tensor pipe) -------
__device__ __forceinline__ void ldmat4(uint32_t r[4], uint32_t addr){
    asm volatile("ldmatrix.sync.aligned.m8n8.x4.shared.b16 {%0,%1,%2,%3}, [%4];"
        : "=r"(r[0]), "=r"(r[1]), "=r"(r[2]), "=r"(r[3]) : "r"(addr));
}
__device__ __forceinline__ void mma16816(float c[4], const uint32_t a[4],
                                         uint32_t b0, uint32_t b1){
    asm volatile("mma.sync.aligned.m16n8k16.row.col.f32.f16.f16.f32 "
        "{%0,%1,%2,%3}, {%4,%5,%6,%7}, {%8,%9}, {%0,%1,%2,%3};"
        : "+f"(c[0]), "+f"(c[1]), "+f"(c[2]), "+f"(c[3])
        : "r"(a[0]), "r"(a[1]), "r"(a[2]), "r"(a[3]), "r"(b0), "r"(b1));
}

// smem tile layout: padded stride 72 fp16 (144B = 9 x 16B -> conflict-free)
#define ASTRIDE 72
#define OFF_AH  0
#define OFF_AL  18432
#define OFF_BH  36864
#define GEMM_SMEM 46080

// ---- 128x64x256 tile: fp16 split via mma.sync, fp32 accumulate ------------
// USE_AL (compile-time): include the Al*Bh correction term (2-term split).
template <bool USE_AL>
__device__ __forceinline__ void tile_mma(const __half* __restrict__ Ah,
                                         const __half* __restrict__ Al,
                                         const __half* __restrict__ Bh,
                                         int m0, float acc[2][4][4])
{
    extern __shared__ char smem[];
    const uint32_t sb = smem_u32(smem);
    const int tid = threadIdx.x;
    const int lane = tid & 31;
    const int wid = tid >> 5;
    const int wm = wid & 3;        // m32 section
    const int wn = wid >> 2;       // n32 section

    #pragma unroll
    for (int mt = 0; mt < 2; ++mt)
        #pragma unroll
        for (int nt = 0; nt < 4; ++nt)
            #pragma unroll
            for (int q = 0; q < 4; ++q) acc[mt][nt][q] = 0.f;

    const uint32_t aoff = (uint32_t)(((lane & 15)*ASTRIDE + (lane >> 4)*8) * 2);
    const uint32_t boff = (uint32_t)((((lane & 7) + ((lane >> 4) << 3))*ASTRIDE
                                      + ((lane >> 3) & 1)*8) * 2);

    constexpr int NV = USE_AL ? 10 : 6;   // copy items: A(4) [+Al(4)] +B(2)

    #pragma unroll 1
    for (int kc = 0; kc < 4; ++kc) {
        #pragma unroll
        for (int i = 0; i < NV; ++i) {
            int v = tid + i*256;
            const uint4* src;
            uint32_t dst;
            if (v < 1024) {
                int row = v >> 3, c8 = v & 7;
                src = (const uint4*)(Ah + (m0 + row)*CDIM + kc*64 + c8*8);
                dst = OFF_AH + (uint32_t)(row*ASTRIDE + c8*8)*2;
            } else if (USE_AL && v < 2048) {
                int u = v - 1024, row = u >> 3, c8 = u & 7;
                src = (const uint4*)(Al + (m0 + row)*CDIM + kc*64 + c8*8);
                dst = OFF_AL + (uint32_t)(row*ASTRIDE + c8*8)*2;
            } else {
                int u = v - (USE_AL ? 2048 : 1024);
                int row = u >> 3, c8 = u & 7;
                src = (const uint4*)(Bh + row*CDIM + kc*64 + c8*8);
                dst = OFF_BH + (uint32_t)(row*ASTRIDE + c8*8)*2;
            }
            *(uint4*)(smem + dst) = *src;
        }
        __syncthreads();

        #pragma unroll
        for (int ks = 0; ks < 4; ++ks) {
            const uint32_t abase = (uint32_t)((wm*32*ASTRIDE + ks*16) * 2);
            const uint32_t bbase = (uint32_t)((wn*32*ASTRIDE + ks*16) * 2);
            const uint32_t mstep = (uint32_t)(16*ASTRIDE*2);

            uint32_t ah0[4], ah1[4];
            ldmat4(ah0, sb + OFF_AH + abase + aoff);
            ldmat4(ah1, sb + OFF_AH + abase + mstep + aoff);

            uint32_t bhA[4], bhB[4];
            ldmat4(bhA, sb + OFF_BH + bbase + boff);
            ldmat4(bhB, sb + OFF_BH + bbase + mstep + boff);

            mma16816(acc[0][0], ah0, bhA[0], bhA[1]);
            mma16816(acc[0][1], ah0, bhA[2], bhA[3]);
            mma16816(acc[0][2], ah0, bhB[0], bhB[1]);
            mma16816(acc[0][3], ah0, bhB[2], bhB[3]);
            mma16816(acc[1][0], ah1, bhA[0], bhA[1]);
            mma16816(acc[1][1], ah1, bhA[2], bhA[3]);
            mma16816(acc[1][2], ah1, bhB[0], bhB[1]);
            mma16816(acc[1][3], ah1, bhB[2], bhB[3]);

            if constexpr (USE_AL) {
                uint32_t al0[4], al1[4];
                ldmat4(al0, sb + OFF_AL + abase + aoff);
                ldmat4(al1, sb + OFF_AL + abase + mstep + aoff);
                mma16816(acc[0][0], al0, bhA[0], bhA[1]);
                mma16816(acc[0][1], al0, bhA[2], bhA[3]);
                mma16816(acc[0][2], al0, bhB[0], bhB[1]);
                mma16816(acc[0][3], al0, bhB[2], bhB[3]);
                mma16816(acc[1][0], al1, bhA[0], bhA[1]);
                mma16816(acc[1][1], al1, bhA[2], bhA[3]);
                mma16816(acc[1][2], al1, bhB[0], bhB[1]);
                mma16816(acc[1][3], al1, bhB[2], bhB[3]);
            }
        }
        __syncthreads();
    }
}

// GEMM1 (fused grid, top-level dispatch):
//   by 0..3 -> m = relu(h Wmlp^T + b)  (fp16 out, 1-term split)
//   by 4..7 -> tmp = h Wa^T            (fp32 out, 2-term split)
__global__ void __launch_bounds__(256) gemm1_kernel(const float* __restrict__ mlp_b,
                                                    float* __restrict__ tmp_out)
{
    int m0 = blockIdx.x * 128;
    int by = blockIdx.y;
    int lane = threadIdx.x & 31, wid = threadIdx.x >> 5;
    int wm = wid & 3, wn = wid >> 2;
    int g = lane >> 2, t = lane & 3;

    if (by < 4) {
        int d0 = by * 64;
        float acc[2][4][4];
        tile_mma<false>(g_Ah, g_Al, g_Wmh + d0*CDIM, m0, acc);

        #pragma unroll
        for (int mt = 0; mt < 2; ++mt) {
            #pragma unroll
            for (int nt = 0; nt < 4; ++nt) {
                int n = d0 + wn*32 + nt*8 + t*2;
                float bx = mlp_b[n], byv = mlp_b[n+1];
                #pragma unroll
                for (int half = 0; half < 2; ++half) {
                    int m = m0 + wm*32 + mt*16 + g + half*8;
                    if (m >= M_TOTAL) continue;
                    float vx = fmaxf(acc[mt][nt][half*2+0] + bx, 0.f);
                    float vy = fmaxf(acc[mt][nt][half*2+1] + byv, 0.f);
                    *(__half2*)(g_m + m*CDIM + n) =
                        __halves2half2(__float2half_rn(vx), __float2half_rn(vy));
                }
            }
        }
    } else {
        int d0 = (by - 4) * 64;
        float acc[2][4][4];
        tile_mma<true>(g_Ah, g_Al, g_Wah + d0*CDIM, m0, acc);

        #pragma unroll
        for (int mt = 0; mt < 2; ++mt) {
            #pragma unroll
            for (int nt = 0; nt < 4; ++nt) {
                int n = d0 + wn*32 + nt*8 + t*2;
                #pragma unroll
                for (int half = 0; half < 2; ++half) {
                    int m = m0 + wm*32 + mt*16 + g + half*8;
                    if (m >= M_TOTAL) continue;
                    *(float2*)(tmp_out + m*CDIM + n) =
                        make_float2(acc[mt][nt][half*2+0], acc[mt][nt][half*2+1]);
                }
            }
        }
    }
}

// GEMM3: h' = relu(tmp + msg Wb^T + b_rnn); writes fp32 h and fp16 split
__global__ void __launch_bounds__(256) gemm3_kernel(const float* __restrict__ rnn_b,
                                                    const float* __restrict__ tmp,
                                                    float* __restrict__ h_out)
{
    int m0 = blockIdx.x * 128;
    int d0 = blockIdx.y * 64;

    float acc[2][4][4];
    tile_mma<true>(g_Mh, g_Ml, g_Wbh + d0*CDIM, m0, acc);

    int lane = threadIdx.x & 31, wid = threadIdx.x >> 5;
    int wm = wid & 3, wn = wid >> 2;
    int g = lane >> 2, t = lane & 3;

    #pragma unroll
    for (int mt = 0; mt < 2; ++mt) {
        #pragma unroll
        for (int nt = 0; nt < 4; ++nt) {
            int n = d0 + wn*32 + nt*8 + t*2;
            float bx = rnn_b[n], byv = rnn_b[n+1];
            #pragma unroll
            for (int half = 0; half < 2; ++half) {
                int m = m0 + wm*32 + mt*16 + g + half*8;
                if (m >= M_TOTAL) continue;
                float2 tv = *(const float2*)(tmp + m*CDIM + n);
                float vx = fmaxf(acc[mt][nt][half*2+0] + tv.x + bx, 0.f);
                float vy = fmaxf(acc[mt][nt][half*2+1] + tv.y + byv, 0.f);
                *(float2*)(h_out + m*CDIM + n) = make_float2(vx, vy);
                __half hx, lx, hy, ly;
                hsplit(vx, hx, lx); hsplit(vy, hy, ly);
                *(__half2*)(g_Ah + m*CDIM + n) = __halves2half2(hx, hy);
                *(__half2*)(g_Al + m*CDIM + n) = __halves2half2(lx, ly);
            }
        }
    }
}

// -------- weight conversion + pad-row zeroing (once per call) --------------
__global__ void __launch_bounds__(256) wconv_kernel(const float* __restrict__ mlp_w,
                                                    const float* __restrict__ rnn_w)
{
    int e = blockIdx.x * 256 + threadIdx.x;   // < 256*768
    if (e < CDIM*CDIM) {
        g_Wmh[e] = __float2half_rn(mlp_w[e]);
    } else {
        int u = e - CDIM*CDIM;                 // < 256*512
        int r = u >> 9, c = u & 511;
        __half h = __float2half_rn(rnn_w[u]);
        if (c < CDIM) g_Wah[r*CDIM + c] = h;
        else          g_Wbh[r*CDIM + c - CDIM] = h;
    }
    if (e < (MPAD - M_TOTAL)*CDIM) {           // zero pad rows (96*256)
        int o = M_TOTAL*CDIM + e;
        g_Ah[o] = __float2half(0.f); g_Al[o] = __float2half(0.f);
        g_Mh[o] = __float2half(0.f); g_Ml[o] = __float2half(0.f);
    }
}

// -- cnn (n,c,s) -> Ah/Al (n,s,c) fp16 split + out[:, :256] copy (fused) ----
__global__ void __launch_bounds__(256) tin_kernel(const float* __restrict__ cnn,
                                                  float* __restrict__ out)
{
    __shared__ float tile[32][65];                   // [s_l][c_l], pad 65
    int s0 = blockIdx.x * 32;
    int c0 = blockIdx.y * 64;
    int bn = blockIdx.z;
    const float* src = cnn + ((size_t)bn*CDIM + c0)*HWP + s0;
    float* dst = out + ((size_t)bn*(2*CDIM) + c0)*HWP + s0;

    #pragma unroll
    for (int i = 0; i < 8; ++i) {
        int flat = threadIdx.x + i*256;              // 0..2047
        int s_l = flat & 31, c_l = flat >> 5;
        float v = 0.f;
        if (s0 + s_l < HWP) {
            v = src[(size_t)c_l*HWP + s_l];
            dst[(size_t)c_l*HWP + s_l] = v;          // out[:, :256] = cnn
        }
        tile[s_l][c_l] = v;
    }
    __syncthreads();

    #pragma unroll
    for (int i = 0; i < 4; ++i) {
        int flat = threadIdx.x + i*256;              // 0..1023 (half2 units)
        int cp = flat & 31;                          // c = cp*2
        int s_l = flat >> 5;
        int s = s0 + s_l;
        if (s >= HWP) continue;
        float v0 = tile[s_l][cp*2], v1 = tile[s_l][cp*2+1];
        __half h0, l0, h1, l1;
        hsplit(v0, h0, l0); hsplit(v1, h1, l1);
        int o = (bn*HWP + s)*CDIM + c0 + cp*2;
        *(__half2*)(g_Ah + o) = __halves2half2(h0, h1);
        *(__half2*)(g_Al + o) = __halves2half2(l0, l1);
    }
}

// ------- h (n,s,c) -> out[:, 256:512] (n,c,s), smem tile transpose ---------
__global__ void __launch_bounds__(256) tout_kernel(const float* __restrict__ h,
                                                   float* __restrict__ out)
{
    __shared__ float tile[64][33];                   // [c_l][s_l], pad 33
    int s0 = blockIdx.x * 32;
    int c0 = blockIdx.y * 64;
    int bn = blockIdx.z;

    #pragma unroll
    for (int i = 0; i < 8; ++i) {
        int flat = threadIdx.x + i*256;
        int c_l = flat & 63, s_l = flat >> 6;        // s_l 0..31
        int s = s0 + s_l;
        float v = 0.f;
        if (s < HWP) v = h[((size_t)bn*HWP + s)*CDIM + c0 + c_l];
        tile[c_l][s_l] = v;
    }
    __syncthreads();

    #pragma unroll
    for (int i = 0; i < 8; ++i) {
        int flat = threadIdx.x + i*256;
        int s_l = flat & 31, c_l = flat >> 5;        // c_l 0..63
        int s = s0 + s_l;
        if (s < HWP)
            out[((size_t)bn*(2*CDIM) + CDIM + c0 + c_l)*HWP + s] = tile[c_l][s_l];
    }
}

// ---------------- KNN v6: candidate-major, 4 rows/block ---------------------
#define KNN_BR 4
#define CAP 192
// dynamic smem layout (bytes)
#define KPX    0                        // float[3600]  14400
#define KPY    14400
#define KPZ    28800                    // end 43200
#define KHIST  43200                    // int[4][256]   4096
#define KCV    47296                    // u32[4][CAP]   3072
#define KCI    50368                    // int[4][CAP]   3072
#define KTIE   53440                    // int[4][32]     512
#define KOCNT  53952                    // int[4]
#define KCCNT  53968                    // int[4]
#define KECRIT 53984                    // int[4]
#define KFLAG  54000                    // int[4]
#define KWS    54016                    // int[2][8]
#define KSC    54080                    // int[4]
#define KNN_SMEM 54144

__global__ void __launch_bounds__(256) knn_kernel(const float* __restrict__ pts,
                                                  int* __restrict__ idx_out)
{
    extern __shared__ char sm[];
    float* px = (float*)(sm + KPX);
    float* py = (float*)(sm + KPY);
    float* pz = (float*)(sm + KPZ);
    int* hist = (int*)(sm + KHIST);
    unsigned* cv = (unsigned*)(sm + KCV);
    int* ci = (int*)(sm + KCI);
    int* tiebuf = (int*)(sm + KTIE);
    int* ocnt  = (int*)(sm + KOCNT);
    int* ccnt  = (int*)(sm + KCCNT);
    int* ecrit = (int*)(sm + KECRIT);
    int* flag  = (int*)(sm + KFLAG);
    int* ws    = (int*)(sm + KWS);
    int* sc    = (int*)(sm + KSC);

    int gb = blockIdx.x;
    int n  = gb / (HWP/KNN_BR);
    int g  = gb % (HWP/KNN_BR);
    int tid = threadIdx.x;
    int lane = tid & 31, wid = tid >> 5;
    const unsigned ltm = (1u << lane) - 1u;

    const float* p = pts + n*3*HWP;
    for (int i = tid; i < HWP; i += 256) {
        px[i] = p[i];
        py[i] = p[i + HWP];
        pz[i] = p[i + 2*HWP];
    }
    #pragma unroll
    for (int i = 0; i < KNN_BR; ++i) hist[i*256 + tid] = 0;
    if (tid < KNN_BR) { ocnt[tid] = 0; ccnt[tid] = 0; flag[tid] = 0; }
    __syncthreads();                                   // B0

    float qx[KNN_BR], qy[KNN_BR], qz[KNN_BR], qs[KNN_BR];
    #pragma unroll
    for (int r = 0; r < KNN_BR; ++r) {
        int row = g*KNN_BR + r;
        qx[r] = px[row]; qy[r] = py[row]; qz[r] = pz[row];
        qs[r] = fmaf(qz[r], qz[r], fmaf(qy[r], qy[r], qx[r]*qx[r]));
    }

    // ---- pass 1: candidate-major, build histograms -------------------------
    #pragma unroll 1
    for (int t = 0; t < 15; ++t) {
        int j = t*256 + tid;
        bool v = j < HWP;
        float x = 0.f, y = 0.f, z = 0.f, sj = 0.f;
        if (v) { x = px[j]; y = py[j]; z = pz[j]; sj = fmaf(z, z, fmaf(y, y, x*x)); }
        #pragma unroll
        for (int r = 0; r < KNN_BR; ++r) {
            unsigned bits = 0x7f800000u;
            if (v) {
                float dot = fmaf(qz[r], z, fmaf(qy[r], y, qx[r]*x));
                bits = __float_as_uint(fmaxf(qs[r] + sj - 2.0f*dot, 0.0f));
            }
            unsigned e = bits >> 23;
            unsigned mask = __match_any_sync(0xffffffffu, e);
            if (lane == (unsigned)(__ffs(mask) - 1)) atomicAdd(&hist[r*256 + e], __popc(mask));
        }
    }
    __syncthreads();                                   // B1

    // ---- scan: warp w scans hist[w] ----------------------------------------
    if (wid < KNN_BR) {
        int* h4 = hist + wid*256;
        int basebin = lane*8, loc[8], ssum = 0;
        #pragma unroll
        for (int j2 = 0; j2 < 8; ++j2) { loc[j2] = h4[basebin + j2]; ssum += loc[j2]; }
        int pre = ssum;
        #pragma unroll
        for (int o = 1; o < 32; o <<= 1) {
            int v2 = __shfl_up_sync(0xffffffffu, pre, o);
            if (lane >= (unsigned)o) pre += v2;
        }
        int excl = pre - ssum;
        int ec = 0;
        if (excl < KNN && excl + ssum >= KNN) {        // unique crossing lane
            int cum = excl;
            #pragma unroll
            for (int j2 = 0; j2 < 8; ++j2) {
                if (cum + loc[j2] >= KNN) { ec = basebin + j2; break; }
                cum += loc[j2];
            }
        }
        ec = __reduce_max_sync(0xffffffffu, ec);
        if (lane == 0) ecrit[wid] = ec;
    }
    __syncthreads();                                   // B2

    int Ereg[KNN_BR];
    #pragma unroll
    for (int r = 0; r < KNN_BR; ++r) Ereg[r] = ecrit[r];

    // ---- pass 2: recompute, ballot-aggregated compaction -------------------
    #pragma unroll 1
    for (int t = 0; t < 15; ++t) {
        int j = t*256 + tid;
        bool v = j < HWP;
        float x = 0.f, y = 0.f, z = 0.f, sj = 0.f;
        if (v) { x = px[j]; y = py[j]; z = pz[j]; sj = fmaf(z, z, fmaf(y, y, x*x)); }
        #pragma unroll
        for (int r = 0; r < KNN_BR; ++r) {
            unsigned bits = 0x7f800000u;
            if (v) {
                float dot = fmaf(qz[r], z, fmaf(qy[r], y, qx[r]*x));
                bits = __float_as_uint(fmaxf(qs[r] + sj - 2.0f*dot, 0.0f));
            }
            int e = (int)(bits >> 23);
            bool win = v && e < Ereg[r];
            unsigned mw = __ballot_sync(0xffffffffu, win);
            if (mw) {
                int src = __ffs(mw) - 1;
                int base = 0;
                if (lane == (unsigned)src) base = atomicAdd(&ocnt[r], __popc(mw));
                base = __shfl_sync(0xffffffffu, base, src);
                if (win) idx_out[(n*HWP + g*KNN_BR + r)*KNN + base + __popc(mw & ltm)] = j;
            }
            bool cand = v && e == Ereg[r];
            unsigned mc = __ballot_sync(0xffffffffu, cand);
            if (mc) {
                int src = __ffs(mc) - 1;
                int base = 0;
                if (lane == (unsigned)src) base = atomicAdd(&ccnt[r], __popc(mc));
                base = __shfl_sync(0xffffffffu, base, src);
                if (cand) {
                    int pos = base + __popc(mc & ltm);
                    if (pos < CAP) { cv[r*CAP + pos] = bits; ci[r*CAP + pos] = j; }
                }
            }
        }
    }
    __syncthreads();                                   // B3

    // ---- phase B: one row per warp (warps 0..3) ------------------------------
    if (wid < KNN_BR) {
        int r = wid;
        int row = g*KNN_BR + r;
        int* outp = idx_out + (n*HWP + row)*KNN;
        unsigned* wcv = cv + r*CAP;
        int* wci = ci + r*CAP;
        int* wtie = tiebuf + r*32;

        int oc0 = ocnt[r], cc = ccnt[r];
        int Kp = KNN - oc0;

        if (cc > CAP) {
            if (lane == 0) flag[r] = 1;
        } else if (cc == Kp) {
            for (int i = lane; i < cc; i += 32) outp[oc0 + i] = wci[i];
        } else {
            unsigned T = ((unsigned)Ereg[r]) << 23;
            for (int bit = 22; bit >= 0; --bit) {
                unsigned cnd = T | (1u << bit);
                int cnt = 0;
                for (int i = lane; i < cc; i += 32) cnt += (wcv[i] < cnd) ? 1 : 0;
                cnt = __reduce_add_sync(0xffffffffu, cnt);
                if (cnt < Kp) T = cnd;
            }
            int oc = oc0, tc = 0;
            for (int ib = 0; ib < cc; ib += 32) {
                int i = ib + lane;
                bool v = i < cc;
                unsigned bv = v ? wcv[i] : 0xffffffffu;
                unsigned mw = __ballot_sync(0xffffffffu, v && bv < T);
                if (v && bv < T) outp[oc + __popc(mw & ltm)] = wci[i];
                oc += __popc(mw);
                unsigned mt = __ballot_sync(0xffffffffu, v && bv == T);
                if (v && bv == T) {
                    int tp = tc + __popc(mt & ltm);
                    if (tp < 32) wtie[tp] = wci[i];
                }
                tc += __popc(mt);
            }
            __syncwarp();
            if (lane == 0) {
                int slots = KNN - oc;
                int en = tc < 32 ? tc : 32;
                for (int q2 = 0; q2 < slots; ++q2) {   // lowest-index tie fill
                    int best = 0x7fffffff, bi = 0;
                    for (int e2 = 0; e2 < en; ++e2)
                        if (wtie[e2] < best) { best = wtie[e2]; bi = e2; }
                    wtie[bi] = 0x7fffffff;
                    outp[oc + q2] = best;
                }
            }
        }
    }
    __syncthreads();

    // ---- fallback: block-wide 31-bit search (rare) --------------------------
    for (int r = 0; r < KNN_BR; ++r) {
        if (!flag[r]) continue;
        int row = g*KNN_BR + r;
        float fqx = qx[r], fqy = qy[r], fqz = qz[r], fqs = qs[r];

        unsigned d[15];
        #pragma unroll
        for (int t = 0; t < 15; ++t) {
            int j = t*256 + tid;
            if (j < HWP) {
                float x = px[j], y = py[j], z = pz[j];
                float sj  = fmaf(z, z, fmaf(y, y, x*x));
                float dot = fmaf(fqz, z, fmaf(fqy, y, fqx*x));
                d[t] = __float_as_uint(fmaxf(fqs + sj - 2.0f*dot, 0.0f));
            } else {
                d[t] = 0xffffffffu;
            }
        }
        if (tid == 0) { sc[0] = 0; sc[1] = 0; }
        __syncthreads();

        unsigned T = 0;
        for (int bit = 30; bit >= 0; --bit) {
            unsigned cnd = T | (1u << bit);
            int cc2 = 0;
            #pragma unroll
            for (int t = 0; t < 15; ++t) cc2 += (d[t] < cnd) ? 1 : 0;
            cc2 = __reduce_add_sync(0xffffffffu, cc2);
            int par = bit & 1;
            if (lane == 0) ws[par*8 + wid] = cc2;
            __syncthreads();
            int tot = 0;
            #pragma unroll
            for (int w = 0; w < 8; ++w) tot += ws[par*8 + w];
            if (tot < KNN) T = cnd;
        }
        __syncthreads();

        int* outp = idx_out + (n*HWP + row)*KNN;
        int* wtie = tiebuf + r*32;
        #pragma unroll
        for (int t = 0; t < 15; ++t) {
            int j = t*256 + tid;
            unsigned dv = d[t];
            if (dv < T) { int pos = atomicAdd(&sc[0], 1); outp[pos] = j; }
            else if (dv == T && j < HWP) { int pos = atomicAdd(&sc[1], 1); if (pos < 32) wtie[pos] = j; }
        }
        __syncthreads();
        if (tid == 0) {
            int slots = KNN - sc[0];
            int en = sc[1] < 32 ? sc[1] : 32;
            for (int q2 = 0; q2 < slots; ++q2) {
                int best = 0x7fffffff, bi = 0;
                for (int e2 = 0; e2 < en; ++e2)
                    if (wtie[e2] < best) { best = wtie[e2]; bi = e2; }
                wtie[bi] = 0x7fffffff;
                outp[sc[0] + q2] = best;
            }
        }
        __syncthreads();
    }
}

// ------- gather-mean v3: 16 pts/block, 32 thr/pt, 16B loads ----------------
__global__ void __launch_bounds__(512) gather_mean_kernel(const int* __restrict__ idx)
{
    __shared__ int sidx[16*KNN];
    int tid = threadIdx.x;
    int s0 = blockIdx.x * 16;
    sidx[tid]       = idx[s0*KNN + tid];
    sidx[tid + 512] = idx[s0*KNN + tid + 512];
    __syncthreads();

    int lp = tid >> 5;          // 0..15 local point
    int lane = tid & 31;        // 16B chunk (8 halves) within row
    int s = s0 + lp;
    int base = (s / HWP) * HWP;
    const uint4* m4 = reinterpret_cast<const uint4*>(g_m);   // 32 uint4 per row
    const int* ip = sidx + lp*KNN;

    float acc[8];
    #pragma unroll
    for (int i = 0; i < 8; ++i) acc[i] = 0.f;

    #pragma unroll
    for (int k = 0; k < KNN; k += 4) {
        int j0 = ip[k], j1 = ip[k+1], j2 = ip[k+2], j3 = ip[k+3];
        uint4 u0 = m4[(size_t)(base + j0)*32 + lane];
        uint4 u1 = m4[(size_t)(base + j1)*32 + lane];
        uint4 u2 = m4[(size_t)(base + j2)*32 + lane];
        uint4 u3 = m4[(size_t)(base + j3)*32 + lane];
        #pragma unroll
        for (int q = 0; q < 4; ++q) {
            uint4 u = (q == 0) ? u0 : (q == 1) ? u1 : (q == 2) ? u2 : u3;
            float2 f0 = __half22float2(*(__half2*)&u.x);
            float2 f1 = __half22float2(*(__half2*)&u.y);
            float2 f2 = __half22float2(*(__half2*)&u.z);
            float2 f3 = __half22float2(*(__half2*)&u.w);
            acc[0] += f0.x; acc[1] += f0.y; acc[2] += f1.x; acc[3] += f1.y;
            acc[4] += f2.x; acc[5] += f2.y; acc[6] += f3.x; acc[7] += f3.y;
        }
    }
    const float inv = 1.0f / 64.0f;
    __half hh[8], ll[8];
    #pragma unroll
    for (int i = 0; i < 8; ++i) hsplit(acc[i]*inv, hh[i], ll[i]);

    int o = s*CDIM + lane*8;
    __half2 mh0 = __halves2half2(hh[0], hh[1]), mh1 = __halves2half2(hh[2], hh[3]);
    __half2 mh2 = __halves2half2(hh[4], hh[5]), mh3 = __halves2half2(hh[6], hh[7]);
    __half2 ml0 = __halves2half2(ll[0], ll[1]), ml1 = __halves2half2(ll[2], ll[3]);
    __half2 ml2 = __halves2half2(ll[4], ll[5]), ml3 = __halves2half2(ll[6], ll[7]);
    uint4 sh, sl;
    sh.x = *(uint32_t*)&mh0; sh.y = *(uint32_t*)&mh1;
    sh.z = *(uint32_t*)&mh2; sh.w = *(uint32_t*)&mh3;
    sl.x = *(uint32_t*)&ml0; sl.y = *(uint32_t*)&ml1;
    sl.z = *(uint32_t*)&ml2; sl.w = *(uint32_t*)&ml3;
    *(uint4*)(g_Mh + o) = sh;
    *(uint4*)(g_Ml + o) = sl;
}

// ---------------- launcher --------------------------------------------------
extern "C" void kernel_launch(void* const* d_in, const int* in_sizes, int n_in,
                              void* d_out, int out_size)
{
    const float* cnn   = (const float*)d_in[0];
    const float* pts   = (const float*)d_in[1];
    const float* mlp_w = (const float*)d_in[2];
    const float* mlp_b = (const float*)d_in[3];
    const float* rnn_w = (const float*)d_in[4];
    const float* rnn_b = (const float*)d_in[5];
    float* out = (float*)d_out;

    float *tmp, *h;
    int* idx;
    cudaGetSymbolAddress((void**)&tmp, g_tmp);
    cudaGetSymbolAddress((void**)&h,   g_h);
    cudaGetSymbolAddress((void**)&idx, g_idx);

    cudaFuncSetAttribute(gemm1_kernel, cudaFuncAttributeMaxDynamicSharedMemorySize, GEMM_SMEM);
    cudaFuncSetAttribute(gemm3_kernel, cudaFuncAttributeMaxDynamicSharedMemorySize, GEMM_SMEM);
    cudaFuncSetAttribute(knn_kernel,   cudaFuncAttributeMaxDynamicSharedMemorySize, KNN_SMEM);

    wconv_kernel<<<768, 256>>>(mlp_w, rnn_w);
    tin_kernel<<<dim3(113, 4, 2), 256>>>(cnn, out);
    knn_kernel<<<NBATCH*(HWP/KNN_BR), 256, KNN_SMEM>>>(pts, idx);

    for (int it = 0; it < 3; ++it) {
        gemm1_kernel<<<dim3(MPAD/128, 8), 256, GEMM_SMEM>>>(mlp_b, tmp);
        gather_mean_kernel<<<M_TOTAL/16, 512>>>(idx);
        gemm3_kernel<<<dim3(MPAD/128, 4), 256, GEMM_SMEM>>>(rnn_b, tmp, h);
    }
    tout_kernel<<<dim3(113, 4, 2), 256>>>(h, out);
}

// round 17
// speedup vs baseline: 1.1103x; 1.0504x over previous
#include <cuda_runtime.h>
#include <cuda_fp16.h>
#include <cstdint>

#define HWP 3600
#define NBATCH 2
#define CDIM 256
#define KNN 64
#define M_TOTAL (NBATCH*HWP)   // 7200
#define MPAD 7296              // padded rows (multiple of 128)

// ---------------- scratch (device globals; no allocation allowed) ----------
__device__ __half g_m[MPAD*CDIM];       // relu(mlp(h)) fp16
__device__ float g_tmp[MPAD*CDIM];      // h @ Wa^T fp32
__device__ float g_h[MPAD*CDIM];        // fp32 h (for final readout)
__device__ __half g_Ah[MPAD*CDIM], g_Al[MPAD*CDIM];   // h split (fp16 hi/lo)
__device__ __half g_Mh[MPAD*CDIM], g_Ml[MPAD*CDIM];   // msg split
__device__ __half g_Wmh[CDIM*CDIM];                   // mlp_w hi
__device__ __half g_Wah[CDIM*CDIM];                   // rnn_w[:, :C] hi
__device__ __half g_Wbh[CDIM*CDIM];                   // rnn_w[:, C:] hi
__device__ int   g_idx[M_TOTAL*KNN];

// fp16 hi/lo split: v ~= h + l with combined 22-bit mantissa
__device__ __forceinline__ void hsplit(float v, __half& h, __half& l){
    h = __float2half_rn(v);
    l = __float2half_rn(v - __half2float(h));
}

__device__ __forceinline__ uint32_t smem_u32(const void* p) {
    uint32_t a;
    asm("{ .reg .u64 t; cvta.to.shared.u64 t, %1; cvt.u32.u64 %0, t; }" : "=r"(a) : "l"(p));
    return a;
}

// ---------------- mma.sync helpers (suffix-neutral PTX, tensor pipe) -------
__device__ __forceinline__ void ldmat4(uint32_t r[4], uint32_t addr){
    asm volatile("ldmatrix.sync.aligned.m8n8.x4.shared.b16 {%0,%1,%2,%3}, [%4];"
        : "=r"(r[0]), "=r"(r[1]), "=r"(r[2]), "=r"(r[3]) : "r"(addr));
}
__device__ __forceinline__ void mma16816(float c[4], const uint32_t a[4],
                                         uint32_t b0, uint32_t b1){
    asm volatile("mma.sync.aligned.m16n8k16.row.col.f32.f16.f16.f32 "
        "{%0,%1,%2,%3}, {%4,%5,%6,%7}, {%8,%9}, {%0,%1,%2,%3};"
        : "+f"(c[0]), "+f"(c[1]), "+f"(c[2]), "+f"(c[3])
        : "r"(a[0]), "r"(a[1]), "r"(a[2]), "r"(a[3]), "r"(b0), "r"(b1));
}

// smem tile layout: padded stride 72 fp16 (144B = 9 x 16B -> conflict-free)
#define ASTRIDE 72
#define OFF_AH  0
#define OFF_AL  18432
#define OFF_BH  36864
#define GEMM_SMEM 46080

// ---- 128x64x256 tile: fp16 2-term split via mma.sync, fp32 accumulate -----
__device__ void tile_mma(const __half* __restrict__ Ah,
                         const __half* __restrict__ Al,
                         const __half* __restrict__ Bh,
                         int m0, float acc[2][4][4])
{
    extern __shared__ char smem[];
    const uint32_t sb = smem_u32(smem);
    const int tid = threadIdx.x;
    const int lane = tid & 31;
    const int wid = tid >> 5;
    const int wm = wid & 3;        // m32 section
    const int wn = wid >> 2;       // n32 section

    #pragma unroll
    for (int mt = 0; mt < 2; ++mt)
        #pragma unroll
        for (int nt = 0; nt < 4; ++nt)
            #pragma unroll
            for (int q = 0; q < 4; ++q) acc[mt][nt][q] = 0.f;

    const uint32_t aoff = (uint32_t)(((lane & 15)*ASTRIDE + (lane >> 4)*8) * 2);
    const uint32_t boff = (uint32_t)((((lane & 7) + ((lane >> 4) << 3))*ASTRIDE
                                      + ((lane >> 3) & 1)*8) * 2);

    #pragma unroll 1
    for (int kc = 0; kc < 4; ++kc) {
        #pragma unroll
        for (int i = 0; i < 10; ++i) {
            int v = tid + i*256;
            const uint4* src;
            uint32_t dst;
            if (v < 1024) {
                int row = v >> 3, c8 = v & 7;
                src = (const uint4*)(Ah + (m0 + row)*CDIM + kc*64 + c8*8);
                dst = OFF_AH + (uint32_t)(row*ASTRIDE + c8*8)*2;
            } else if (v < 2048) {
                int u = v - 1024, row = u >> 3, c8 = u & 7;
                src = (const uint4*)(Al + (m0 + row)*CDIM + kc*64 + c8*8);
                dst = OFF_AL + (uint32_t)(row*ASTRIDE + c8*8)*2;
            } else {
                int u = v - 2048, row = u >> 3, c8 = u & 7;
                src = (const uint4*)(Bh + row*CDIM + kc*64 + c8*8);
                dst = OFF_BH + (uint32_t)(row*ASTRIDE + c8*8)*2;
            }
            *(uint4*)(smem + dst) = *src;
        }
        __syncthreads();

        #pragma unroll
        for (int ks = 0; ks < 4; ++ks) {
            const uint32_t abase = (uint32_t)((wm*32*ASTRIDE + ks*16) * 2);
            const uint32_t bbase = (uint32_t)((wn*32*ASTRIDE + ks*16) * 2);
            const uint32_t mstep = (uint32_t)(16*ASTRIDE*2);

            uint32_t ah0[4], ah1[4];
            ldmat4(ah0, sb + OFF_AH + abase + aoff);
            ldmat4(ah1, sb + OFF_AH + abase + mstep + aoff);

            uint32_t bhA[4], bhB[4];
            ldmat4(bhA, sb + OFF_BH + bbase + boff);
            ldmat4(bhB, sb + OFF_BH + bbase + mstep + boff);

            mma16816(acc[0][0], ah0, bhA[0], bhA[1]);
            mma16816(acc[0][1], ah0, bhA[2], bhA[3]);
            mma16816(acc[0][2], ah0, bhB[0], bhB[1]);
            mma16816(acc[0][3], ah0, bhB[2], bhB[3]);
            mma16816(acc[1][0], ah1, bhA[0], bhA[1]);
            mma16816(acc[1][1], ah1, bhA[2], bhA[3]);
            mma16816(acc[1][2], ah1, bhB[0], bhB[1]);
            mma16816(acc[1][3], ah1, bhB[2], bhB[3]);

            uint32_t al0[4], al1[4];
            ldmat4(al0, sb + OFF_AL + abase + aoff);
            ldmat4(al1, sb + OFF_AL + abase + mstep + aoff);
            mma16816(acc[0][0], al0, bhA[0], bhA[1]);
            mma16816(acc[0][1], al0, bhA[2], bhA[3]);
            mma16816(acc[0][2], al0, bhB[0], bhB[1]);
            mma16816(acc[0][3], al0, bhB[2], bhB[3]);
            mma16816(acc[1][0], al1, bhA[0], bhA[1]);
            mma16816(acc[1][1], al1, bhA[2], bhA[3]);
            mma16816(acc[1][2], al1, bhB[0], bhB[1]);
            mma16816(acc[1][3], al1, bhB[2], bhB[3]);
        }
        __syncthreads();
    }
}

// GEMM1: by 0..3 -> m = relu(h Wmlp^T + b) (fp16);  by 4..7 -> tmp = h Wa^T
__global__ void __launch_bounds__(256) gemm1_kernel(const float* __restrict__ mlp_b,
                                                    float* __restrict__ tmp_out)
{
    int m0 = blockIdx.x * 128;
    int by = blockIdx.y;
    bool is_m = by < 4;
    int d0 = (is_m ? by : by - 4) * 64;
    const __half* Bh = (is_m ? g_Wmh : g_Wah) + d0*CDIM;

    float acc[2][4][4];
    tile_mma(g_Ah, g_Al, Bh, m0, acc);

    int lane = threadIdx.x & 31, wid = threadIdx.x >> 5;
    int wm = wid & 3, wn = wid >> 2;
    int g = lane >> 2, t = lane & 3;

    #pragma unroll
    for (int mt = 0; mt < 2; ++mt) {
        #pragma unroll
        for (int nt = 0; nt < 4; ++nt) {
            int nl = wn*32 + nt*8 + t*2;
            int n = d0 + nl;
            float bx = 0.f, byv = 0.f;
            if (is_m) { bx = mlp_b[n]; byv = mlp_b[n+1]; }
            #pragma unroll
            for (int half = 0; half < 2; ++half) {
                int m = m0 + wm*32 + mt*16 + g + half*8;
                if (m >= M_TOTAL) continue;
                float vx = acc[mt][nt][half*2+0];
                float vy = acc[mt][nt][half*2+1];
                if (is_m) {
                    vx = fmaxf(vx + bx, 0.f);
                    vy = fmaxf(vy + byv, 0.f);
                    *(__half2*)(g_m + m*CDIM + n) =
                        __halves2half2(__float2half_rn(vx), __float2half_rn(vy));
                } else {
                    *(float2*)(tmp_out + m*CDIM + n) = make_float2(vx, vy);
                }
            }
        }
    }
}

// GEMM3: h' = relu(tmp + msg Wb^T + b_rnn); writes fp32 h (+ fp16 split
// unless last iteration, where Ah/Al are never read again)
template <bool WRITE_SPLIT>
__global__ void __launch_bounds__(256) gemm3_kernel(const float* __restrict__ rnn_b,
                                                    const float* __restrict__ tmp,
                                                    float* __restrict__ h_out)
{
    int m0 = blockIdx.x * 128;
    int d0 = blockIdx.y * 64;

    float acc[2][4][4];
    tile_mma(g_Mh, g_Ml, g_Wbh + d0*CDIM, m0, acc);

    int lane = threadIdx.x & 31, wid = threadIdx.x >> 5;
    int wm = wid & 3, wn = wid >> 2;
    int g = lane >> 2, t = lane & 3;

    #pragma unroll
    for (int mt = 0; mt < 2; ++mt) {
        #pragma unroll
        for (int nt = 0; nt < 4; ++nt) {
            int n = d0 + wn*32 + nt*8 + t*2;
            float bx = rnn_b[n], byv = rnn_b[n+1];
            #pragma unroll
            for (int half = 0; half < 2; ++half) {
                int m = m0 + wm*32 + mt*16 + g + half*8;
                if (m >= M_TOTAL) continue;
                float2 tv = *(const float2*)(tmp + m*CDIM + n);
                float vx = fmaxf(acc[mt][nt][half*2+0] + tv.x + bx, 0.f);
                float vy = fmaxf(acc[mt][nt][half*2+1] + tv.y + byv, 0.f);
                *(float2*)(h_out + m*CDIM + n) = make_float2(vx, vy);
                if constexpr (WRITE_SPLIT) {
                    __half hx, lx, hy, ly;
                    hsplit(vx, hx, lx); hsplit(vy, hy, ly);
                    *(__half2*)(g_Ah + m*CDIM + n) = __halves2half2(hx, hy);
                    *(__half2*)(g_Al + m*CDIM + n) = __halves2half2(lx, ly);
                }
            }
        }
    }
}

// -------- weight conversion + pad-row zeroing (once per call) --------------
__global__ void __launch_bounds__(256) wconv_kernel(const float* __restrict__ mlp_w,
                                                    const float* __restrict__ rnn_w)
{
    int e = blockIdx.x * 256 + threadIdx.x;   // < 256*768
    if (e < CDIM*CDIM) {
        g_Wmh[e] = __float2half_rn(mlp_w[e]);
    } else {
        int u = e - CDIM*CDIM;                 // < 256*512
        int r = u >> 9, c = u & 511;
        __half h = __float2half_rn(rnn_w[u]);
        if (c < CDIM) g_Wah[r*CDIM + c] = h;
        else          g_Wbh[r*CDIM + c - CDIM] = h;
    }
    if (e < (MPAD - M_TOTAL)*CDIM) {           // zero pad rows (96*256)
        int o = M_TOTAL*CDIM + e;
        g_Ah[o] = __float2half(0.f); g_Al[o] = __float2half(0.f);
        g_Mh[o] = __float2half(0.f); g_Ml[o] = __float2half(0.f);
    }
}

// -- cnn (n,c,s) -> Ah/Al (n,s,c) fp16 split + out[:, :256] copy (fused) ----
__global__ void __launch_bounds__(256) tin_kernel(const float* __restrict__ cnn,
                                                  float* __restrict__ out)
{
    __shared__ float tile[32][65];                   // [s_l][c_l], pad 65
    int s0 = blockIdx.x * 32;
    int c0 = blockIdx.y * 64;
    int bn = blockIdx.z;
    const float* src = cnn + ((size_t)bn*CDIM + c0)*HWP + s0;
    float* dst = out + ((size_t)bn*(2*CDIM) + c0)*HWP + s0;

    #pragma unroll
    for (int i = 0; i < 8; ++i) {
        int flat = threadIdx.x + i*256;              // 0..2047
        int s_l = flat & 31, c_l = flat >> 5;
        float v = 0.f;
        if (s0 + s_l < HWP) {
            v = src[(size_t)c_l*HWP + s_l];
            dst[(size_t)c_l*HWP + s_l] = v;          // out[:, :256] = cnn
        }
        tile[s_l][c_l] = v;
    }
    __syncthreads();

    #pragma unroll
    for (int i = 0; i < 4; ++i) {
        int flat = threadIdx.x + i*256;              // 0..1023 (half2 units)
        int cp = flat & 31;                          // c = cp*2
        int s_l = flat >> 5;
        int s = s0 + s_l;
        if (s >= HWP) continue;
        float v0 = tile[s_l][cp*2], v1 = tile[s_l][cp*2+1];
        __half h0, l0, h1, l1;
        hsplit(v0, h0, l0); hsplit(v1, h1, l1);
        int o = (bn*HWP + s)*CDIM + c0 + cp*2;
        *(__half2*)(g_Ah + o) = __halves2half2(h0, h1);
        *(__half2*)(g_Al + o) = __halves2half2(l0, l1);
    }
}

// ------- h (n,s,c) -> out[:, 256:512] (n,c,s), smem tile transpose ---------
__global__ void __launch_bounds__(256) tout_kernel(const float* __restrict__ h,
                                                   float* __restrict__ out)
{
    __shared__ float tile[64][33];                   // [c_l][s_l], pad 33
    int s0 = blockIdx.x * 32;
    int c0 = blockIdx.y * 64;
    int bn = blockIdx.z;

    #pragma unroll
    for (int i = 0; i < 8; ++i) {
        int flat = threadIdx.x + i*256;
        int c_l = flat & 63, s_l = flat >> 6;        // s_l 0..31
        int s = s0 + s_l;
        float v = 0.f;
        if (s < HWP) v = h[((size_t)bn*HWP + s)*CDIM + c0 + c_l];
        tile[c_l][s_l] = v;
    }
    __syncthreads();

    #pragma unroll
    for (int i = 0; i < 8; ++i) {
        int flat = threadIdx.x + i*256;
        int s_l = flat & 31, c_l = flat >> 5;        // c_l 0..63
        int s = s0 + s_l;
        if (s < HWP)
            out[((size_t)bn*(2*CDIM) + CDIM + c0 + c_l)*HWP + s] = tile[c_l][s_l];
    }
}

// ---------------- KNN v6: candidate-major, 4 rows/block ---------------------
#define KNN_BR 4
#define CAP 192
// dynamic smem layout (bytes)
#define KPX    0                        // float[3600]  14400
#define KPY    14400
#define KPZ    28800                    // end 43200
#define KHIST  43200                    // int[4][256]   4096
#define KCV    47296                    // u32[4][CAP]   3072
#define KCI    50368                    // int[4][CAP]   3072
#define KTIE   53440                    // int[4][32]     512
#define KOCNT  53952                    // int[4]
#define KCCNT  53968                    // int[4]
#define KECRIT 53984                    // int[4]
#define KFLAG  54000                    // int[4]
#define KWS    54016                    // int[2][8]
#define KSC    54080                    // int[4]
#define KNN_SMEM 54144

__global__ void __launch_bounds__(256) knn_kernel(const float* __restrict__ pts,
                                                  int* __restrict__ idx_out)
{
    extern __shared__ char sm[];
    float* px = (float*)(sm + KPX);
    float* py = (float*)(sm + KPY);
    float* pz = (float*)(sm + KPZ);
    int* hist = (int*)(sm + KHIST);
    unsigned* cv = (unsigned*)(sm + KCV);
    int* ci = (int*)(sm + KCI);
    int* tiebuf = (int*)(sm + KTIE);
    int* ocnt  = (int*)(sm + KOCNT);
    int* ccnt  = (int*)(sm + KCCNT);
    int* ecrit = (int*)(sm + KECRIT);
    int* flag  = (int*)(sm + KFLAG);
    int* ws    = (int*)(sm + KWS);
    int* sc    = (int*)(sm + KSC);

    int gb = blockIdx.x;
    int n  = gb / (HWP/KNN_BR);
    int g  = gb % (HWP/KNN_BR);
    int tid = threadIdx.x;
    int lane = tid & 31, wid = tid >> 5;
    const unsigned ltm = (1u << lane) - 1u;

    const float* p = pts + n*3*HWP;
    for (int i = tid; i < HWP; i += 256) {
        px[i] = p[i];
        py[i] = p[i + HWP];
        pz[i] = p[i + 2*HWP];
    }
    #pragma unroll
    for (int i = 0; i < KNN_BR; ++i) hist[i*256 + tid] = 0;
    if (tid < KNN_BR) { ocnt[tid] = 0; ccnt[tid] = 0; flag[tid] = 0; }
    __syncthreads();                                   // B0

    float qx[KNN_BR], qy[KNN_BR], qz[KNN_BR], qs[KNN_BR];
    #pragma unroll
    for (int r = 0; r < KNN_BR; ++r) {
        int row = g*KNN_BR + r;
        qx[r] = px[row]; qy[r] = py[row]; qz[r] = pz[row];
        qs[r] = fmaf(qz[r], qz[r], fmaf(qy[r], qy[r], qx[r]*qx[r]));
    }

    // ---- pass 1: candidate-major, build histograms -------------------------
    #pragma unroll 1
    for (int t = 0; t < 15; ++t) {
        int j = t*256 + tid;
        bool v = j < HWP;
        float x = 0.f, y = 0.f, z = 0.f, sj = 0.f;
        if (v) { x = px[j]; y = py[j]; z = pz[j]; sj = fmaf(z, z, fmaf(y, y, x*x)); }
        #pragma unroll
        for (int r = 0; r < KNN_BR; ++r) {
            unsigned bits = 0x7f800000u;
            if (v) {
                float dot = fmaf(qz[r], z, fmaf(qy[r], y, qx[r]*x));
                bits = __float_as_uint(fmaxf(qs[r] + sj - 2.0f*dot, 0.0f));
            }
            unsigned e = bits >> 23;
            unsigned mask = __match_any_sync(0xffffffffu, e);
            if (lane == (unsigned)(__ffs(mask) - 1)) atomicAdd(&hist[r*256 + e], __popc(mask));
        }
    }
    __syncthreads();                                   // B1

    // ---- scan: warp w scans hist[w] ----------------------------------------
    if (wid < KNN_BR) {
        int* h4 = hist + wid*256;
        int basebin = lane*8, loc[8], ssum = 0;
        #pragma unroll
        for (int j2 = 0; j2 < 8; ++j2) { loc[j2] = h4[basebin + j2]; ssum += loc[j2]; }
        int pre = ssum;
        #pragma unroll
        for (int o = 1; o < 32; o <<= 1) {
            int v2 = __shfl_up_sync(0xffffffffu, pre, o);
            if (lane >= (unsigned)o) pre += v2;
        }
        int excl = pre - ssum;
        int ec = 0;
        if (excl < KNN && excl + ssum >= KNN) {        // unique crossing lane
            int cum = excl;
            #pragma unroll
            for (int j2 = 0; j2 < 8; ++j2) {
                if (cum + loc[j2] >= KNN) { ec = basebin + j2; break; }
                cum += loc[j2];
            }
        }
        ec = __reduce_max_sync(0xffffffffu, ec);
        if (lane == 0) ecrit[wid] = ec;
    }
    __syncthreads();                                   // B2

    int Ereg[KNN_BR];
    #pragma unroll
    for (int r = 0; r < KNN_BR; ++r) Ereg[r] = ecrit[r];

    // ---- pass 2: recompute, ballot-aggregated compaction -------------------
    #pragma unroll 1
    for (int t = 0; t < 15; ++t) {
        int j = t*256 + tid;
        bool v = j < HWP;
        float x = 0.f, y = 0.f, z = 0.f, sj = 0.f;
        if (v) { x = px[j]; y = py[j]; z = pz[j]; sj = fmaf(z, z, fmaf(y, y, x*x)); }
        #pragma unroll
        for (int r = 0; r < KNN_BR; ++r) {
            unsigned bits = 0x7f800000u;
            if (v) {
                float dot = fmaf(qz[r], z, fmaf(qy[r], y, qx[r]*x));
                bits = __float_as_uint(fmaxf(qs[r] + sj - 2.0f*dot, 0.0f));
            }
            int e = (int)(bits >> 23);
            bool win = v && e < Ereg[r];
            unsigned mw = __ballot_sync(0xffffffffu, win);
            if (mw) {
                int src = __ffs(mw) - 1;
                int base = 0;
                if (lane == (unsigned)src) base = atomicAdd(&ocnt[r], __popc(mw));
                base = __shfl_sync(0xffffffffu, base, src);
                if (win) idx_out[(n*HWP + g*KNN_BR + r)*KNN + base + __popc(mw & ltm)] = j;
            }
            bool cand = v && e == Ereg[r];
            unsigned mc = __ballot_sync(0xffffffffu, cand);
            if (mc) {
                int src = __ffs(mc) - 1;
                int base = 0;
                if (lane == (unsigned)src) base = atomicAdd(&ccnt[r], __popc(mc));
                base = __shfl_sync(0xffffffffu, base, src);
                if (cand) {
                    int pos = base + __popc(mc & ltm);
                    if (pos < CAP) { cv[r*CAP + pos] = bits; ci[r*CAP + pos] = j; }
                }
            }
        }
    }
    __syncthreads();                                   // B3

    // ---- phase B: one row per warp (warps 0..3) ------------------------------
    if (wid < KNN_BR) {
        int r = wid;
        int row = g*KNN_BR + r;
        int* outp = idx_out + (n*HWP + row)*KNN;
        unsigned* wcv = cv + r*CAP;
        int* wci = ci + r*CAP;
        int* wtie = tiebuf + r*32;

        int oc0 = ocnt[r], cc = ccnt[r];
        int Kp = KNN - oc0;

        if (cc > CAP) {
            if (lane == 0) flag[r] = 1;
        } else if (cc == Kp) {
            for (int i = lane; i < cc; i += 32) outp[oc0 + i] = wci[i];
        } else {
            unsigned T = ((unsigned)Ereg[r]) << 23;
            for (int bit = 22; bit >= 0; --bit) {
                unsigned cnd = T | (1u << bit);
                int cnt = 0;
                for (int i = lane; i < cc; i += 32) cnt += (wcv[i] < cnd) ? 1 : 0;
                cnt = __reduce_add_sync(0xffffffffu, cnt);
                if (cnt < Kp) T = cnd;
            }
            int oc = oc0, tc = 0;
            for (int ib = 0; ib < cc; ib += 32) {
                int i = ib + lane;
                bool v = i < cc;
                unsigned bv = v ? wcv[i] : 0xffffffffu;
                unsigned mw = __ballot_sync(0xffffffffu, v && bv < T);
                if (v && bv < T) outp[oc + __popc(mw & ltm)] = wci[i];
                oc += __popc(mw);
                unsigned mt = __ballot_sync(0xffffffffu, v && bv == T);
                if (v && bv == T) {
                    int tp = tc + __popc(mt & ltm);
                    if (tp < 32) wtie[tp] = wci[i];
                }
                tc += __popc(mt);
            }
            __syncwarp();
            if (lane == 0) {
                int slots = KNN - oc;
                int en = tc < 32 ? tc : 32;
                for (int q2 = 0; q2 < slots; ++q2) {   // lowest-index tie fill
                    int best = 0x7fffffff, bi = 0;
                    for (int e2 = 0; e2 < en; ++e2)
                        if (wtie[e2] < best) { best = wtie[e2]; bi = e2; }
                    wtie[bi] = 0x7fffffff;
                    outp[oc + q2] = best;
                }
            }
        }
    }
    __syncthreads();

    // ---- fallback: block-wide 31-bit search (rare) --------------------------
    for (int r = 0; r < KNN_BR; ++r) {
        if (!flag[r]) continue;
        int row = g*KNN_BR + r;
        float fqx = qx[r], fqy = qy[r], fqz = qz[r], fqs = qs[r];

        unsigned d[15];
        #pragma unroll
        for (int t = 0; t < 15; ++t) {
            int j = t*256 + tid;
            if (j < HWP) {
                float x = px[j], y = py[j], z = pz[j];
                float sj  = fmaf(z, z, fmaf(y, y, x*x));
                float dot = fmaf(fqz, z, fmaf(fqy, y, fqx*x));
                d[t] = __float_as_uint(fmaxf(fqs + sj - 2.0f*dot, 0.0f));
            } else {
                d[t] = 0xffffffffu;
            }
        }
        if (tid == 0) { sc[0] = 0; sc[1] = 0; }
        __syncthreads();

        unsigned T = 0;
        for (int bit = 30; bit >= 0; --bit) {
            unsigned cnd = T | (1u << bit);
            int cc2 = 0;
            #pragma unroll
            for (int t = 0; t < 15; ++t) cc2 += (d[t] < cnd) ? 1 : 0;
            cc2 = __reduce_add_sync(0xffffffffu, cc2);
            int par = bit & 1;
            if (lane == 0) ws[par*8 + wid] = cc2;
            __syncthreads();
            int tot = 0;
            #pragma unroll
            for (int w = 0; w < 8; ++w) tot += ws[par*8 + w];
            if (tot < KNN) T = cnd;
        }
        __syncthreads();

        int* outp = idx_out + (n*HWP + row)*KNN;
        int* wtie = tiebuf + r*32;
        #pragma unroll
        for (int t = 0; t < 15; ++t) {
            int j = t*256 + tid;
            unsigned dv = d[t];
            if (dv < T) { int pos = atomicAdd(&sc[0], 1); outp[pos] = j; }
            else if (dv == T && j < HWP) { int pos = atomicAdd(&sc[1], 1); if (pos < 32) wtie[pos] = j; }
        }
        __syncthreads();
        if (tid == 0) {
            int slots = KNN - sc[0];
            int en = sc[1] < 32 ? sc[1] : 32;
            for (int q2 = 0; q2 < slots; ++q2) {
                int best = 0x7fffffff, bi = 0;
                for (int e2 = 0; e2 < en; ++e2)
                    if (wtie[e2] < best) { best = wtie[e2]; bi = e2; }
                wtie[bi] = 0x7fffffff;
                outp[sc[0] + q2] = best;
            }
        }
        __syncthreads();
    }
}

// ------- gather-mean v3: 16 pts/block, 32 thr/pt, 16B loads ----------------
__global__ void __launch_bounds__(512) gather_mean_kernel(const int* __restrict__ idx)
{
    __shared__ int sidx[16*KNN];
    int tid = threadIdx.x;
    int s0 = blockIdx.x * 16;
    sidx[tid]       = idx[s0*KNN + tid];
    sidx[tid + 512] = idx[s0*KNN + tid + 512];
    __syncthreads();

    int lp = tid >> 5;          // 0..15 local point
    int lane = tid & 31;        // 16B chunk (8 halves) within row
    int s = s0 + lp;
    int base = (s / HWP) * HWP;
    const uint4* m4 = reinterpret_cast<const uint4*>(g_m);   // 32 uint4 per row
    const int* ip = sidx + lp*KNN;

    float acc[8];
    #pragma unroll
    for (int i = 0; i < 8; ++i) acc[i] = 0.f;

    #pragma unroll
    for (int k = 0; k < KNN; k += 4) {
        int j0 = ip[k], j1 = ip[k+1], j2 = ip[k+2], j3 = ip[k+3];
        uint4 u0 = m4[(size_t)(base + j0)*32 + lane];
        uint4 u1 = m4[(size_t)(base + j1)*32 + lane];
        uint4 u2 = m4[(size_t)(base + j2)*32 + lane];
        uint4 u3 = m4[(size_t)(base + j3)*32 + lane];
        #pragma unroll
        for (int q = 0; q < 4; ++q) {
            uint4 u = (q == 0) ? u0 : (q == 1) ? u1 : (q == 2) ? u2 : u3;
            float2 f0 = __half22float2(*(__half2*)&u.x);
            float2 f1 = __half22float2(*(__half2*)&u.y);
            float2 f2 = __half22float2(*(__half2*)&u.z);
            float2 f3 = __half22float2(*(__half2*)&u.w);
            acc[0] += f0.x; acc[1] += f0.y; acc[2] += f1.x; acc[3] += f1.y;
            acc[4] += f2.x; acc[5] += f2.y; acc[6] += f3.x; acc[7] += f3.y;
        }
    }
    const float inv = 1.0f / 64.0f;
    __half hh[8], ll[8];
    #pragma unroll
    for (int i = 0; i < 8; ++i) hsplit(acc[i]*inv, hh[i], ll[i]);

    int o = s*CDIM + lane*8;
    __half2 mh0 = __halves2half2(hh[0], hh[1]), mh1 = __halves2half2(hh[2], hh[3]);
    __half2 mh2 = __halves2half2(hh[4], hh[5]), mh3 = __halves2half2(hh[6], hh[7]);
    __half2 ml0 = __halves2half2(ll[0], ll[1]), ml1 = __halves2half2(ll[2], ll[3]);
    __half2 ml2 = __halves2half2(ll[4], ll[5]), ml3 = __halves2half2(ll[6], ll[7]);
    uint4 sh, sl;
    sh.x = *(uint32_t*)&mh0; sh.y = *(uint32_t*)&mh1;
    sh.z = *(uint32_t*)&mh2; sh.w = *(uint32_t*)&mh3;
    sl.x = *(uint32_t*)&ml0; sl.y = *(uint32_t*)&ml1;
    sl.z = *(uint32_t*)&ml2; sl.w = *(uint32_t*)&ml3;
    *(uint4*)(g_Mh + o) = sh;
    *(uint4*)(g_Ml + o) = sl;
}

// ---------------- launcher --------------------------------------------------
extern "C" void kernel_launch(void* const* d_in, const int* in_sizes, int n_in,
                              void* d_out, int out_size)
{
    const float* cnn   = (const float*)d_in[0];
    const float* pts   = (const float*)d_in[1];
    const float* mlp_w = (const float*)d_in[2];
    const float* mlp_b = (const float*)d_in[3];
    const float* rnn_w = (const float*)d_in[4];
    const float* rnn_b = (const float*)d_in[5];
    float* out = (float*)d_out;

    float *tmp, *h;
    int* idx;
    cudaGetSymbolAddress((void**)&tmp, g_tmp);
    cudaGetSymbolAddress((void**)&h,   g_h);
    cudaGetSymbolAddress((void**)&idx, g_idx);

    cudaFuncSetAttribute(gemm1_kernel, cudaFuncAttributeMaxDynamicSharedMemorySize, GEMM_SMEM);
    cudaFuncSetAttribute(gemm3_kernel<true>,  cudaFuncAttributeMaxDynamicSharedMemorySize, GEMM_SMEM);
    cudaFuncSetAttribute(gemm3_kernel<false>, cudaFuncAttributeMaxDynamicSharedMemorySize, GEMM_SMEM);
    cudaFuncSetAttribute(knn_kernel,   cudaFuncAttributeMaxDynamicSharedMemorySize, KNN_SMEM);

    // fork: run knn concurrently with wconv/tin/gemm1[0] (no dependency
    // until the first gather). Capture-safe fork/join via events.
    cudaStream_t s2;
    cudaStreamCreateWithFlags(&s2, cudaStreamNonBlocking);
    cudaEvent_t evFork, evJoin;
    cudaEventCreateWithFlags(&evFork, cudaEventDisableTiming);
    cudaEventCreateWithFlags(&evJoin, cudaEventDisableTiming);

    cudaEventRecord(evFork, 0);
    cudaStreamWaitEvent(s2, evFork, 0);
    knn_kernel<<<NBATCH*(HWP/KNN_BR), 256, KNN_SMEM, s2>>>(pts, idx);
    cudaEventRecord(evJoin, s2);

    wconv_kernel<<<768, 256>>>(mlp_w, rnn_w);
    tin_kernel<<<dim3(113, 4, 2), 256>>>(cnn, out);

    // iter 0 (gemm1 overlaps knn; gather joins)
    gemm1_kernel<<<dim3(MPAD/128, 8), 256, GEMM_SMEM>>>(mlp_b, tmp);
    cudaStreamWaitEvent(0, evJoin, 0);
    gather_mean_kernel<<<M_TOTAL/16, 512>>>(idx);
    gemm3_kernel<true><<<dim3(MPAD/128, 4), 256, GEMM_SMEM>>>(rnn_b, tmp, h);
    // iter 1
    gemm1_kernel<<<dim3(MPAD/128, 8), 256, GEMM_SMEM>>>(mlp_b, tmp);
    gather_mean_kernel<<<M_TOTAL/16, 512>>>(idx);
    gemm3_kernel<true><<<dim3(MPAD/128, 4), 256, GEMM_SMEM>>>(rnn_b, tmp, h);
    // iter 2 (skip Ah/Al split writes; nothing reads them afterwards)
    gemm1_kernel<<<dim3(MPAD/128, 8), 256, GEMM_SMEM>>>(mlp_b, tmp);
    gather_mean_kernel<<<M_TOTAL/16, 512>>>(idx);
    gemm3_kernel<false><<<dim3(MPAD/128, 4), 256, GEMM_SMEM>>>(rnn_b, tmp, h);

    tout_kernel<<<dim3(113, 4, 2), 256>>>(h, out);
}